// round 4
// baseline (speedup 1.0000x reference)
#include <cuda_runtime.h>
#include <cstdint>
#include <cstring>

// ============================================================
// LSTM on GB300, base-target ISA only (no tcgen05 — harness
// compiles PTX for sm_103 non-'a').
//  - int8 split-quantization: h*127 = h1 + h2/256,
//    w/s = w1 + w2/256  (s = wmax/127, global scale)
//    z = S1*(h1W1) + S2*(h1W2 + h2W1), S2 = S1/256, int32 exact.
//  - mma.sync.m16n8k32.s8 (IMMA), 2 accumulator tiles.
//  - ONE persistent kernel for all 256 steps:
//      * W resident in SMEM (loaded once)
//      * c state resident in registers
//      * grid-wide spin barrier between steps (128 CTAs,
//        all co-resident on 148 SMs)
//  - P-table kills the input GEMM (VOCAB=10).
//  - x dtype detected at runtime (int32 vs int64) and
//    canonicalized to int32 in g_x.
// ============================================================

constexpr int BATCH = 256;
constexpr int SEQ   = 256;
constexpr int HID   = 1024;
constexpr int G4    = 4096;
constexpr int NTILE = 64;
constexpr int MTILE = 128;
constexpr int KC    = 128;            // K bytes per chunk
constexpr int NCH   = HID / KC;       // 8 chunks
constexpr int WPITCH = 1040;          // 1024 + 16 pad
constexpr int APITCH = 144;           // 128 + 16 pad
constexpr int ZPITCH = 68;            // floats

constexpr int SM_W1 = 0;
constexpr int SM_W2 = SM_W1 + NTILE * WPITCH;   // 66560
constexpr int SM_A  = SM_W2 + NTILE * WPITCH;   // 133120
constexpr int A1SZ  = MTILE * APITCH;           // 18432
constexpr int STAGE = 2 * A1SZ;                 // 36864 (A1 + A2)
constexpr int SM_Z  = SM_A;                     // z-buffer aliases stage 0
constexpr int SMEM_TOTAL = SM_A + 2 * STAGE;    // 206848 bytes

// ---------------- persistent device state ----------------
__device__ int8_t g_W1[(size_t)G4 * HID];       // 4 MB
__device__ int8_t g_W2[(size_t)G4 * HID];       // 4 MB
__device__ float  g_P[(size_t)10 * G4];         // permuted xproj table
__device__ int8_t g_h1[2][(size_t)BATCH * HID];
__device__ int8_t g_h2[2][(size_t)BATCH * HID];
__device__ int    g_x[BATCH * SEQ];             // canonical int32 tokens
__device__ unsigned g_absmax;
__device__ unsigned g_bar;

// ---------------- helpers ----------------
__device__ __forceinline__ uint32_t smem_u32(const void* p) {
    uint32_t a;
    asm("{ .reg .u64 t; cvta.to.shared.u64 t, %1; cvt.u32.u64 %0, t; }" : "=r"(a) : "l"(p));
    return a;
}
__device__ __forceinline__ void cp16(uint32_t dst, const void* src) {
    asm volatile("cp.async.cg.shared.global [%0], [%1], 16;" :: "r"(dst), "l"(src));
}
__device__ __forceinline__ void ldm_x4(uint32_t* r, uint32_t addr) {
    asm volatile("ldmatrix.sync.aligned.m8n8.x4.shared.b16 {%0,%1,%2,%3}, [%4];"
        : "=r"(r[0]), "=r"(r[1]), "=r"(r[2]), "=r"(r[3]) : "r"(addr));
}
__device__ __forceinline__ void ldm_x2(uint32_t* r, uint32_t addr) {
    asm volatile("ldmatrix.sync.aligned.m8n8.x2.shared.b16 {%0,%1}, [%2];"
        : "=r"(r[0]), "=r"(r[1]) : "r"(addr));
}
__device__ __forceinline__ void mma_s8(int* d, const uint32_t* a, const uint32_t* b) {
    asm volatile("mma.sync.aligned.m16n8k32.row.col.s32.s8.s8.s32 "
        "{%0,%1,%2,%3}, {%4,%5,%6,%7}, {%8,%9}, {%0,%1,%2,%3};"
        : "+r"(d[0]), "+r"(d[1]), "+r"(d[2]), "+r"(d[3])
        : "r"(a[0]), "r"(a[1]), "r"(a[2]), "r"(a[3]), "r"(b[0]), "r"(b[1]));
}
__device__ __forceinline__ float sigf(float x) { return __fdividef(1.0f, 1.0f + __expf(-x)); }
__device__ __forceinline__ float tanhf_(float x) { return 2.0f * sigf(2.0f * x) - 1.0f; }

// ---------------- prep kernels ----------------
__global__ void zero_kernel() {
    int i = blockIdx.x * blockDim.x + threadIdx.x;
    if (i < BATCH * HID) {
        g_h1[0][i] = 0;
        g_h2[0][i] = 0;
    }
    if (i == 0) { g_absmax = 0u; g_bar = 0u; }
}

// Detect whether x is int64 or int32 and canonicalize to g_x (int32).
// If int64 (values 0..9), every odd 32-bit word of the first 256KB is 0.
__global__ void detect_convert_x(const void* xs) {
    __shared__ unsigned acc[256];
    const unsigned* w = (const unsigned*)xs;
    unsigned o = 0;
    for (int i = threadIdx.x; i < BATCH * SEQ / 2; i += 256) o |= w[2 * i + 1];
    acc[threadIdx.x] = o;
    __syncthreads();
    for (int s = 128; s > 0; s >>= 1) {
        if (threadIdx.x < s) acc[threadIdx.x] |= acc[threadIdx.x + s];
        __syncthreads();
    }
    if (acc[0] == 0u) {   // int64 layout
        const long long* p = (const long long*)xs;
        for (int i = threadIdx.x; i < BATCH * SEQ; i += 256) g_x[i] = (int)p[i];
    } else {              // int32 layout
        const int* p = (const int*)xs;
        for (int i = threadIdx.x; i < BATCH * SEQ; i += 256) g_x[i] = p[i];
    }
}

__global__ void wmax_kernel(const float* __restrict__ Wgh, const float* __restrict__ Wih,
                            const float* __restrict__ Wfh, const float* __restrict__ Woh) {
    const float* Ws[4] = {Wgh, Wih, Wfh, Woh};
    float m = 0.0f;
    int stride = gridDim.x * blockDim.x;
    int base = blockIdx.x * blockDim.x + threadIdx.x;
    for (int w = 0; w < 4; w++) {
        const float* W = Ws[w];
        for (int i = base; i < HID * HID; i += stride) m = fmaxf(m, fabsf(W[i]));
    }
#pragma unroll
    for (int off = 16; off > 0; off >>= 1)
        m = fmaxf(m, __shfl_xor_sync(0xffffffffu, m, off));
    if ((threadIdx.x & 31) == 0)
        atomicMax(&g_absmax, __float_as_uint(m));
}

// column n -> (gate = (n%64)/16, j = (n/64)*16 + n%16)
__global__ void prep_kernel(const float* __restrict__ Wgx, const float* __restrict__ Wix,
                            const float* __restrict__ Wfx, const float* __restrict__ Wox,
                            const float* __restrict__ Wgh, const float* __restrict__ Wih,
                            const float* __restrict__ Wfh, const float* __restrict__ Woh,
                            const float* __restrict__ embed,
                            const float* __restrict__ bg, const float* __restrict__ bi,
                            const float* __restrict__ bf_, const float* __restrict__ bo) {
    int n = blockIdx.x;
    int within = n & 63;
    int gate = within >> 4;
    int j = ((n >> 6) << 4) + (within & 15);

    float wmax = __uint_as_float(g_absmax);
    float inv = 127.0f / wmax;

    const float* Wh = gate == 0 ? Wgh : gate == 1 ? Wih : gate == 2 ? Wfh : Woh;
    const float* src = Wh + (size_t)j * HID;
    int8_t* d1 = g_W1 + (size_t)n * HID;
    int8_t* d2 = g_W2 + (size_t)n * HID;
    for (int k = threadIdx.x; k < HID; k += blockDim.x) {
        float q = src[k] * inv;
        float w1 = rintf(q);
        w1 = fminf(fmaxf(w1, -127.0f), 127.0f);
        float w2 = rintf((q - w1) * 256.0f);
        w2 = fminf(fmaxf(w2, -127.0f), 127.0f);
        d1[k] = (int8_t)w1;
        d2[k] = (int8_t)w2;
    }
    if (threadIdx.x < 10) {
        int v = threadIdx.x;
        const float* Wx = gate == 0 ? Wgx : gate == 1 ? Wix : gate == 2 ? Wfx : Wox;
        const float* bb = gate == 0 ? bg : gate == 1 ? bi : gate == 2 ? bf_ : bo;
        float s = bb[j];
#pragma unroll
        for (int e = 0; e < 10; e++) s += Wx[j * 10 + e] * embed[v * 10 + e];
        g_P[(size_t)v * G4 + n] = s;
    }
}

// ---------------- persistent LSTM kernel ----------------
__global__ __launch_bounds__(256, 1) void lstm_persist() {
    extern __shared__ char sm[];
    uint32_t sb = smem_u32(sm);
    int tid = threadIdx.x;
    int lane = tid & 31, wid = tid >> 5;
    int wm = wid & 3, wn = wid >> 2;          // warps: 4 (M) x 2 (N); tile 32x32
    int ntile = blockIdx.x;                   // 0..63
    int m0 = blockIdx.y * MTILE;              // 0 or 128
    int n0 = ntile * NTILE;

    // ---- load W (both splits) into SMEM once ----
    for (int i = tid; i < NTILE * 64; i += 256) {
        int r = i >> 6, s16 = i & 63;
        cp16(sb + SM_W1 + r * WPITCH + s16 * 16, g_W1 + (size_t)(n0 + r) * HID + s16 * 16);
        cp16(sb + SM_W2 + r * WPITCH + s16 * 16, g_W2 + (size_t)(n0 + r) * HID + s16 * 16);
    }
    asm volatile("cp.async.commit_group;" ::: "memory");
    asm volatile("cp.async.wait_group 0;" ::: "memory");
    __syncthreads();

    float wmax = __uint_as_float(g_absmax);
    float S1 = wmax * (1.0f / (127.0f * 127.0f));
    float S2 = S1 * (1.0f / 256.0f);

    // epilogue ownership: thread -> (b_local = tid/2, 8 j's)
    int b_local = tid >> 1;
    int jb = (tid & 1) * 8;
    int b_g = m0 + b_local;
    float creg[8];
#pragma unroll
    for (int q = 0; q < 8; q++) creg[q] = 0.0f;

    // ldmatrix lane address components
    int a_row_l = (lane & 7) + ((lane >> 3) & 1) * 8;
    int a_k_l = ((lane >> 4) & 1) * 16;
    int l2 = lane & 15;
    int b_row_l = l2 & 7;
    int b_k_l = (l2 >> 3) * 16;

    float* zb = (float*)(sm + SM_Z);

    for (int t = 0; t < SEQ; t++) {
        const int8_t* h1g = g_h1[t & 1] + (size_t)m0 * HID;
        const int8_t* h2g = g_h2[t & 1] + (size_t)m0 * HID;

        int accM[2][4][4], accC[2][4][4];
#pragma unroll
        for (int mf = 0; mf < 2; mf++)
#pragma unroll
            for (int nf = 0; nf < 4; nf++)
#pragma unroll
                for (int e = 0; e < 4; e++) { accM[mf][nf][e] = 0; accC[mf][nf][e] = 0; }

        auto load_chunk = [&](int stg, int kc) {
            uint32_t dst = sb + SM_A + stg * STAGE;
            const int8_t* s1 = h1g + kc * KC;
            const int8_t* s2 = h2g + kc * KC;
#pragma unroll
            for (int i = 0; i < 4; i++) {
                int idx = tid + (i << 8);
                int r = idx >> 3, s16 = idx & 7;
                cp16(dst + r * APITCH + s16 * 16, s1 + (size_t)r * HID + s16 * 16);
                cp16(dst + A1SZ + r * APITCH + s16 * 16, s2 + (size_t)r * HID + s16 * 16);
            }
            asm volatile("cp.async.commit_group;" ::: "memory");
        };

        load_chunk(0, 0);

        for (int kc = 0; kc < NCH; kc++) {
            if (kc + 1 < NCH) {
                load_chunk((kc + 1) & 1, kc + 1);
                asm volatile("cp.async.wait_group 1;" ::: "memory");
            } else {
                asm volatile("cp.async.wait_group 0;" ::: "memory");
            }
            __syncthreads();
            uint32_t As = sb + SM_A + (kc & 1) * STAGE;
#pragma unroll
            for (int ks = 0; ks < 4; ks++) {
                uint32_t A1f[2][4], A2f[2][4], B1f[4][2], B2f[4][2];
                int kbw = kc * KC + ks * 32;
                int kba = ks * 32;
#pragma unroll
                for (int mf = 0; mf < 2; mf++) {
                    uint32_t addr = As + (uint32_t)((wm * 32 + mf * 16 + a_row_l) * APITCH + kba + a_k_l);
                    ldm_x4(A1f[mf], addr);
                    ldm_x4(A2f[mf], addr + A1SZ);
                }
#pragma unroll
                for (int nf = 0; nf < 4; nf++) {
                    uint32_t ba = sb + SM_W1 + (uint32_t)((wn * 32 + nf * 8 + b_row_l) * WPITCH + kbw + b_k_l);
                    ldm_x2(B1f[nf], ba);
                    ldm_x2(B2f[nf], ba + (SM_W2 - SM_W1));
                }
#pragma unroll
                for (int mf = 0; mf < 2; mf++)
#pragma unroll
                    for (int nf = 0; nf < 4; nf++) {
                        mma_s8(accM[mf][nf], A1f[mf], B1f[nf]);
                        mma_s8(accC[mf][nf], A1f[mf], B2f[nf]);
                        mma_s8(accC[mf][nf], A2f[mf], B1f[nf]);
                    }
            }
            __syncthreads();
        }

        // ---- exchange z through SMEM ----
        {
            int r0 = (lane >> 2), c0 = (lane & 3) * 2;
#pragma unroll
            for (int mf = 0; mf < 2; mf++)
#pragma unroll
                for (int nf = 0; nf < 4; nf++) {
                    int row = wm * 32 + mf * 16 + r0;
                    int col = wn * 32 + nf * 8 + c0;
                    zb[row * ZPITCH + col]           = S1 * (float)accM[mf][nf][0] + S2 * (float)accC[mf][nf][0];
                    zb[row * ZPITCH + col + 1]       = S1 * (float)accM[mf][nf][1] + S2 * (float)accC[mf][nf][1];
                    zb[(row + 8) * ZPITCH + col]     = S1 * (float)accM[mf][nf][2] + S2 * (float)accC[mf][nf][2];
                    zb[(row + 8) * ZPITCH + col + 1] = S1 * (float)accM[mf][nf][3] + S2 * (float)accC[mf][nf][3];
                }
        }
        __syncthreads();

        // ---- epilogue: gates, c/h update, requantize ----
        {
            int v = g_x[b_g * SEQ + t];
            const float* Pr = g_P + (size_t)v * G4 + n0;
            union { int8_t b[8]; long long ll; } q1, q2;
            const float* zrow = zb + b_local * ZPITCH;
#pragma unroll
            for (int jj = 0; jj < 8; jj++) {
                int j = jb + jj;
                float zg = zrow[j]      + Pr[j];
                float zi = zrow[16 + j] + Pr[16 + j];
                float zf = zrow[32 + j] + Pr[32 + j];
                float zo = zrow[48 + j] + Pr[48 + j];
                float g  = tanhf_(zg);
                float ig = sigf(zi);
                float fg = sigf(zf);
                float og = sigf(zo);
                float cn = g * ig + creg[jj] * fg;
                creg[jj] = cn;
                float h = tanhf_(cn) * og;
                float qq = h * 127.0f;
                float r1 = rintf(qq);
                r1 = fminf(fmaxf(r1, -127.0f), 127.0f);
                float r2 = rintf((qq - r1) * 256.0f);
                r2 = fminf(fmaxf(r2, -127.0f), 127.0f);
                q1.b[jj] = (int8_t)r1;
                q2.b[jj] = (int8_t)r2;
            }
            size_t ho = (size_t)b_g * HID + ntile * 16 + jb;
            *(long long*)(g_h1[(t + 1) & 1] + ho) = q1.ll;
            *(long long*)(g_h2[(t + 1) & 1] + ho) = q2.ll;
        }

        // ---- grid barrier ----
        __threadfence();
        __syncthreads();
        if (tid == 0) {
            atomicAdd(&g_bar, 1u);
            unsigned tgt = 128u * (unsigned)(t + 1);
            unsigned vv;
            do {
                asm volatile("ld.acquire.gpu.u32 %0, [%1];" : "=r"(vv) : "l"(&g_bar));
            } while (vv < tgt);
        }
        __syncthreads();
    }
}

// ---------------- final projection ----------------
__global__ void final_proj_kernel(const float* __restrict__ Wp, const float* __restrict__ bp,
                                  float* __restrict__ out) {
    int b = blockIdx.x;
    int tid = threadIdx.x;   // 128
    const int8_t* h1 = g_h1[0] + (size_t)b * HID;
    const int8_t* h2 = g_h2[0] + (size_t)b * HID;
    float acc[10];
#pragma unroll
    for (int c = 0; c < 10; c++) acc[c] = 0.0f;
    for (int k = tid; k < HID; k += 128) {
        float h = ((float)h1[k] + (float)h2[k] * (1.0f / 256.0f)) * (1.0f / 127.0f);
#pragma unroll
        for (int c = 0; c < 10; c++) acc[c] += h * Wp[c * HID + k];
    }
#pragma unroll
    for (int c = 0; c < 10; c++)
#pragma unroll
        for (int off = 16; off > 0; off >>= 1)
            acc[c] += __shfl_xor_sync(0xffffffffu, acc[c], off);
    __shared__ float red[4][10];
    int wid = tid >> 5, lid = tid & 31;
    if (lid == 0) {
#pragma unroll
        for (int c = 0; c < 10; c++) red[wid][c] = acc[c];
    }
    __syncthreads();
    if (tid < 10)
        out[b * 10 + tid] = red[0][tid] + red[1][tid] + red[2][tid] + red[3][tid] + bp[tid];
}

// ---------------- launch ----------------
extern "C" void kernel_launch(void* const* d_in, const int* in_sizes, int n_in,
                              void* d_out, int out_size) {
    const void*  x   = d_in[0];
    const float* embed = (const float*)d_in[1];
    const float* Wgx = (const float*)d_in[2];
    const float* Wix = (const float*)d_in[3];
    const float* Wfx = (const float*)d_in[4];
    const float* Wox = (const float*)d_in[5];
    const float* Wgh = (const float*)d_in[6];
    const float* Wih = (const float*)d_in[7];
    const float* Wfh = (const float*)d_in[8];
    const float* Woh = (const float*)d_in[9];
    const float* Wph = (const float*)d_in[10];
    const float* bg  = (const float*)d_in[11];
    const float* bi  = (const float*)d_in[12];
    const float* bf_ = (const float*)d_in[13];
    const float* bo  = (const float*)d_in[14];
    const float* bp  = (const float*)d_in[15];

    cudaFuncSetAttribute(lstm_persist, cudaFuncAttributeMaxDynamicSharedMemorySize, SMEM_TOTAL);

    zero_kernel<<<(BATCH * HID + 255) / 256, 256>>>();
    detect_convert_x<<<1, 256>>>(x);
    wmax_kernel<<<512, 256>>>(Wgh, Wih, Wfh, Woh);
    prep_kernel<<<G4, 128>>>(Wgx, Wix, Wfx, Wox, Wgh, Wih, Wfh, Woh, embed, bg, bi, bf_, bo);

    dim3 grid(G4 / NTILE, BATCH / MTILE);   // (64, 2) = 128 CTAs, all resident
    lstm_persist<<<grid, 256, SMEM_TOTAL>>>();

    final_proj_kernel<<<BATCH, 128>>>(Wph, bp, (float*)d_out);
}

// round 5
// speedup vs baseline: 4.1257x; 4.1257x over previous
#include <cuda_runtime.h>
#include <cuda_fp16.h>
#include <cstdint>
#include <cstring>

// ============================================================
// LSTM on GB300, base-target ISA (no tcgen05 available).
// R5: single-pass fp16 HMMA (m16n8k16, fp32 accum) replaces the
// 3-pass int8 split — 3x fewer tensor ops at identical bytes.
//  - ONE persistent kernel, all 256 steps:
//      * W (fp16, permuted) resident in SMEM
//      * c state in registers
//      * grid-wide spin barrier between steps (128 CTAs)
//  - h double-buffered in global memory as fp16.
//  - P-table kills the input GEMM (VOCAB=10).
//  - 4-stage cp.async ring for the h (A) tiles.
// ============================================================

constexpr int BATCH = 256;
constexpr int SEQ   = 256;
constexpr int HID   = 1024;
constexpr int G4    = 4096;
constexpr int NTILE = 64;
constexpr int MTILE = 128;
constexpr int KCE   = 64;             // K elems (fp16) per chunk = 128 bytes
constexpr int NCH   = HID / KCE;      // 16 chunks
constexpr int WPITCH = 2064;          // 2048 + 16 (conflict-free ldmatrix)
constexpr int APITCH = 144;           // 128 + 16
constexpr int ZPITCH = 68;            // floats

constexpr int SM_W  = 0;
constexpr int SM_A  = NTILE * WPITCH;            // 132096
constexpr int ACHUNK = MTILE * APITCH;           // 18432
constexpr int NSTAGE = 4;
constexpr int SM_Z  = SM_A;                      // z aliases stages 0-1 (34816 B)
constexpr int SMEM_TOTAL = SM_A + NSTAGE * ACHUNK;  // 205824

// ---------------- persistent device state ----------------
__device__ __half g_Wf[(size_t)G4 * HID];        // 8 MB, permuted fp16 weights
__device__ float  g_P[(size_t)10 * G4];          // permuted xproj table
__device__ __half g_hf[2][(size_t)BATCH * HID];  // h double buffer (fp16)
__device__ int    g_x[BATCH * SEQ];              // canonical int32 tokens
__device__ unsigned g_bar;

// ---------------- helpers ----------------
__device__ __forceinline__ uint32_t smem_u32(const void* p) {
    uint32_t a;
    asm("{ .reg .u64 t; cvta.to.shared.u64 t, %1; cvt.u32.u64 %0, t; }" : "=r"(a) : "l"(p));
    return a;
}
__device__ __forceinline__ void cp16(uint32_t dst, const void* src) {
    asm volatile("cp.async.cg.shared.global [%0], [%1], 16;" :: "r"(dst), "l"(src));
}
__device__ __forceinline__ void ldm_x4(uint32_t* r, uint32_t addr) {
    asm volatile("ldmatrix.sync.aligned.m8n8.x4.shared.b16 {%0,%1,%2,%3}, [%4];"
        : "=r"(r[0]), "=r"(r[1]), "=r"(r[2]), "=r"(r[3]) : "r"(addr));
}
__device__ __forceinline__ void ldm_x2(uint32_t* r, uint32_t addr) {
    asm volatile("ldmatrix.sync.aligned.m8n8.x2.shared.b16 {%0,%1}, [%2];"
        : "=r"(r[0]), "=r"(r[1]) : "r"(addr));
}
__device__ __forceinline__ void mma_f16(float* d, const uint32_t* a, const uint32_t* b) {
    asm volatile("mma.sync.aligned.m16n8k16.row.col.f32.f16.f16.f32 "
        "{%0,%1,%2,%3}, {%4,%5,%6,%7}, {%8,%9}, {%0,%1,%2,%3};"
        : "+f"(d[0]), "+f"(d[1]), "+f"(d[2]), "+f"(d[3])
        : "r"(a[0]), "r"(a[1]), "r"(a[2]), "r"(a[3]), "r"(b[0]), "r"(b[1]));
}
__device__ __forceinline__ float sigf(float x) { return __fdividef(1.0f, 1.0f + __expf(-x)); }
__device__ __forceinline__ float tanhf_(float x) { return 2.0f * sigf(2.0f * x) - 1.0f; }

// ---------------- prep kernels ----------------
__global__ void zero_kernel() {
    int i = blockIdx.x * blockDim.x + threadIdx.x;
    if (i < BATCH * HID) g_hf[0][i] = __float2half(0.0f);
    if (i == 0) g_bar = 0u;
}

// Detect whether x is int64 or int32 and canonicalize to g_x (int32).
__global__ void detect_convert_x(const void* xs) {
    __shared__ unsigned acc[256];
    const unsigned* w = (const unsigned*)xs;
    unsigned o = 0;
    for (int i = threadIdx.x; i < BATCH * SEQ / 2; i += 256) o |= w[2 * i + 1];
    acc[threadIdx.x] = o;
    __syncthreads();
    for (int s = 128; s > 0; s >>= 1) {
        if (threadIdx.x < s) acc[threadIdx.x] |= acc[threadIdx.x + s];
        __syncthreads();
    }
    if (acc[0] == 0u) {   // int64 layout
        const long long* p = (const long long*)xs;
        for (int i = threadIdx.x; i < BATCH * SEQ; i += 256) g_x[i] = (int)p[i];
    } else {              // int32 layout
        const int* p = (const int*)xs;
        for (int i = threadIdx.x; i < BATCH * SEQ; i += 256) g_x[i] = p[i];
    }
}

// column n -> (gate = (n%64)/16, j = (n/64)*16 + n%16)
__global__ void prep_kernel(const float* __restrict__ Wgx, const float* __restrict__ Wix,
                            const float* __restrict__ Wfx, const float* __restrict__ Wox,
                            const float* __restrict__ Wgh, const float* __restrict__ Wih,
                            const float* __restrict__ Wfh, const float* __restrict__ Woh,
                            const float* __restrict__ embed,
                            const float* __restrict__ bg, const float* __restrict__ bi,
                            const float* __restrict__ bf_, const float* __restrict__ bo) {
    int n = blockIdx.x;
    int within = n & 63;
    int gate = within >> 4;
    int j = ((n >> 6) << 4) + (within & 15);

    const float* Wh = gate == 0 ? Wgh : gate == 1 ? Wih : gate == 2 ? Wfh : Woh;
    const float* src = Wh + (size_t)j * HID;
    __half* d = g_Wf + (size_t)n * HID;
    for (int k = threadIdx.x; k < HID; k += blockDim.x)
        d[k] = __float2half(src[k]);

    if (threadIdx.x < 10) {
        int v = threadIdx.x;
        const float* Wx = gate == 0 ? Wgx : gate == 1 ? Wix : gate == 2 ? Wfx : Wox;
        const float* bb = gate == 0 ? bg : gate == 1 ? bi : gate == 2 ? bf_ : bo;
        float s = bb[j];
#pragma unroll
        for (int e = 0; e < 10; e++) s += Wx[j * 10 + e] * embed[v * 10 + e];
        g_P[(size_t)v * G4 + n] = s;
    }
}

// ---------------- persistent LSTM kernel ----------------
__global__ __launch_bounds__(256, 1) void lstm_persist() {
    extern __shared__ char sm[];
    uint32_t sb = smem_u32(sm);
    int tid = threadIdx.x;
    int lane = tid & 31, wid = tid >> 5;
    int wm = wid & 3, wn = wid >> 2;          // warps: 4 (M) x 2 (N); tile 32x32
    int ntile = blockIdx.x;                   // 0..63
    int m0 = blockIdx.y * MTILE;              // 0 or 128
    int n0 = ntile * NTILE;

    // ---- load W (fp16, full K) into SMEM once: 64 rows x 2048B ----
    for (int i = tid; i < NTILE * 128; i += 256) {
        int r = i >> 7, s16 = i & 127;
        cp16(sb + SM_W + r * WPITCH + s16 * 16,
             g_Wf + (size_t)(n0 + r) * HID + s16 * 8);
    }
    asm volatile("cp.async.commit_group;" ::: "memory");
    asm volatile("cp.async.wait_group 0;" ::: "memory");
    __syncthreads();

    // epilogue ownership: thread -> (b_local = tid/2, 8 j's)
    int b_local = tid >> 1;
    int jb = (tid & 1) * 8;
    int b_g = m0 + b_local;
    float creg[8];
#pragma unroll
    for (int q = 0; q < 8; q++) creg[q] = 0.0f;

    // ldmatrix lane address components (validated in int8 run; byte-identical)
    int a_row_l = (lane & 7) + ((lane >> 3) & 1) * 8;
    int a_k_l = ((lane >> 4) & 1) * 16;
    int l2 = lane & 15;
    int b_row_l = l2 & 7;
    int b_k_l = (l2 >> 3) * 16;

    float* zb = (float*)(sm + SM_Z);

    for (int t = 0; t < SEQ; t++) {
        const __half* hg = g_hf[t & 1] + (size_t)m0 * HID;

        float acc[2][4][4];
#pragma unroll
        for (int mf = 0; mf < 2; mf++)
#pragma unroll
            for (int nf = 0; nf < 4; nf++)
#pragma unroll
                for (int e = 0; e < 4; e++) acc[mf][nf][e] = 0.0f;

        auto load_chunk = [&](int kc) {
            uint32_t dst = sb + SM_A + (kc & (NSTAGE - 1)) * ACHUNK;
            const __half* s = hg + kc * KCE;
#pragma unroll
            for (int i = 0; i < 4; i++) {
                int idx = tid + (i << 8);
                int r = idx >> 3, c16 = idx & 7;
                cp16(dst + r * APITCH + c16 * 16, s + (size_t)r * HID + c16 * 8);
            }
            asm volatile("cp.async.commit_group;" ::: "memory");
        };

        load_chunk(0);
        load_chunk(1);
        load_chunk(2);

        for (int kc = 0; kc < NCH; kc++) {
            if (kc < NCH - 2)      asm volatile("cp.async.wait_group 2;" ::: "memory");
            else if (kc == NCH - 2) asm volatile("cp.async.wait_group 1;" ::: "memory");
            else                    asm volatile("cp.async.wait_group 0;" ::: "memory");
            __syncthreads();
            if (kc + 3 < NCH) load_chunk(kc + 3);

            uint32_t As = sb + SM_A + (kc & (NSTAGE - 1)) * ACHUNK;
#pragma unroll
            for (int ks = 0; ks < 4; ks++) {
                uint32_t Af[2][4], Bf[4][2];
                int kba = ks * 32;                       // bytes within chunk row
                int kbw = kc * 128 + ks * 32;            // bytes within W row
#pragma unroll
                for (int mf = 0; mf < 2; mf++)
                    ldm_x4(Af[mf], As + (uint32_t)((wm * 32 + mf * 16 + a_row_l) * APITCH + kba + a_k_l));
#pragma unroll
                for (int nf = 0; nf < 4; nf++)
                    ldm_x2(Bf[nf], sb + SM_W + (uint32_t)((wn * 32 + nf * 8 + b_row_l) * WPITCH + kbw + b_k_l));
#pragma unroll
                for (int mf = 0; mf < 2; mf++)
#pragma unroll
                    for (int nf = 0; nf < 4; nf++)
                        mma_f16(acc[mf][nf], Af[mf], Bf[nf]);
            }
            __syncthreads();
        }

        // ---- exchange z through SMEM (aliases A stages 0-1; all consumed) ----
        {
            int r0 = (lane >> 2), c0 = (lane & 3) * 2;
#pragma unroll
            for (int mf = 0; mf < 2; mf++)
#pragma unroll
                for (int nf = 0; nf < 4; nf++) {
                    int row = wm * 32 + mf * 16 + r0;
                    int col = wn * 32 + nf * 8 + c0;
                    zb[row * ZPITCH + col]           = acc[mf][nf][0];
                    zb[row * ZPITCH + col + 1]       = acc[mf][nf][1];
                    zb[(row + 8) * ZPITCH + col]     = acc[mf][nf][2];
                    zb[(row + 8) * ZPITCH + col + 1] = acc[mf][nf][3];
                }
        }
        __syncthreads();

        // ---- epilogue: gates, c/h update, fp16 store ----
        {
            int v = g_x[b_g * SEQ + t];
            const float* Pr = g_P + (size_t)v * G4 + n0;
            const float* zrow = zb + b_local * ZPITCH;
            __half hh[8];
#pragma unroll
            for (int jj = 0; jj < 8; jj++) {
                int j = jb + jj;
                float zg = zrow[j]      + Pr[j];
                float zi = zrow[16 + j] + Pr[16 + j];
                float zf = zrow[32 + j] + Pr[32 + j];
                float zo = zrow[48 + j] + Pr[48 + j];
                float g  = tanhf_(zg);
                float ig = sigf(zi);
                float fg = sigf(zf);
                float og = sigf(zo);
                float cn = g * ig + creg[jj] * fg;
                creg[jj] = cn;
                hh[jj] = __float2half(tanhf_(cn) * og);
            }
            size_t ho = (size_t)b_g * HID + ntile * 16 + jb;
            *(uint4*)(g_hf[(t + 1) & 1] + ho) = *(const uint4*)hh;
        }

        // ---- grid barrier ----
        __threadfence();
        __syncthreads();
        if (tid == 0) {
            atomicAdd(&g_bar, 1u);
            unsigned tgt = 128u * (unsigned)(t + 1);
            unsigned vv;
            do {
                asm volatile("ld.acquire.gpu.u32 %0, [%1];" : "=r"(vv) : "l"(&g_bar));
            } while (vv < tgt);
        }
        __syncthreads();
    }
}

// ---------------- final projection ----------------
__global__ void final_proj_kernel(const float* __restrict__ Wp, const float* __restrict__ bp,
                                  float* __restrict__ out) {
    int b = blockIdx.x;
    int tid = threadIdx.x;   // 128
    const __half* h = g_hf[0] + (size_t)b * HID;   // after 256 steps, h in buf 0
    float acc[10];
#pragma unroll
    for (int c = 0; c < 10; c++) acc[c] = 0.0f;
    for (int k = tid; k < HID; k += 128) {
        float hv = __half2float(h[k]);
#pragma unroll
        for (int c = 0; c < 10; c++) acc[c] += hv * Wp[c * HID + k];
    }
#pragma unroll
    for (int c = 0; c < 10; c++)
#pragma unroll
        for (int off = 16; off > 0; off >>= 1)
            acc[c] += __shfl_xor_sync(0xffffffffu, acc[c], off);
    __shared__ float red[4][10];
    int wid = tid >> 5, lid = tid & 31;
    if (lid == 0) {
#pragma unroll
        for (int c = 0; c < 10; c++) red[wid][c] = acc[c];
    }
    __syncthreads();
    if (tid < 10)
        out[b * 10 + tid] = red[0][tid] + red[1][tid] + red[2][tid] + red[3][tid] + bp[tid];
}

// ---------------- launch ----------------
extern "C" void kernel_launch(void* const* d_in, const int* in_sizes, int n_in,
                              void* d_out, int out_size) {
    const void*  x   = d_in[0];
    const float* embed = (const float*)d_in[1];
    const float* Wgx = (const float*)d_in[2];
    const float* Wix = (const float*)d_in[3];
    const float* Wfx = (const float*)d_in[4];
    const float* Wox = (const float*)d_in[5];
    const float* Wgh = (const float*)d_in[6];
    const float* Wih = (const float*)d_in[7];
    const float* Wfh = (const float*)d_in[8];
    const float* Woh = (const float*)d_in[9];
    const float* Wph = (const float*)d_in[10];
    const float* bg  = (const float*)d_in[11];
    const float* bi  = (const float*)d_in[12];
    const float* bf_ = (const float*)d_in[13];
    const float* bo  = (const float*)d_in[14];
    const float* bp  = (const float*)d_in[15];

    cudaFuncSetAttribute(lstm_persist, cudaFuncAttributeMaxDynamicSharedMemorySize, SMEM_TOTAL);

    zero_kernel<<<(BATCH * HID + 255) / 256, 256>>>();
    detect_convert_x<<<1, 256>>>(x);
    prep_kernel<<<G4, 128>>>(Wgx, Wix, Wfx, Wox, Wgh, Wih, Wfh, Woh, embed, bg, bi, bf_, bo);

    dim3 grid(G4 / NTILE, BATCH / MTILE);   // (64, 2) = 128 CTAs, all resident
    lstm_persist<<<grid, 256, SMEM_TOTAL>>>();

    final_proj_kernel<<<BATCH, 128>>>(Wph, bp, (float*)d_out);
}

// round 6
// speedup vs baseline: 4.9836x; 1.2080x over previous
#include <cuda_runtime.h>
#include <cuda_fp16.h>
#include <cstdint>
#include <cstring>

// ============================================================
// LSTM on GB300, base-target ISA (no tcgen05 available).
// R6: 512 threads/CTA, warps 4M x 2N x 2K (K-split) — doubles
// warp-level parallelism to hide legacy-HMMA latency; single
// __syncthreads per K-iteration (8 iters vs 16x2 syncs).
//  - ONE persistent kernel, all 256 steps; W in SMEM; c in regs;
//    grid-wide spin barrier (128 CTAs co-resident).
//  - h double-buffered in global fp16; P-table input GEMM.
// ============================================================

constexpr int BATCH = 256;
constexpr int SEQ   = 256;
constexpr int HID   = 1024;
constexpr int G4    = 4096;
constexpr int NTILE = 64;
constexpr int MTILE = 128;
constexpr int KCE   = 64;             // K elems (fp16) per chunk = 128 bytes
constexpr int NCH   = HID / KCE;      // 16 chunks (8 per K-group)
constexpr int WPITCH = 2064;          // 2048 + 16 (conflict-free ldmatrix)
constexpr int APITCH = 144;           // 128 + 16
constexpr int ZPITCH = 68;            // floats
constexpr int THREADS = 512;

constexpr int SM_W  = 0;
constexpr int SM_A  = NTILE * WPITCH;            // 132096
constexpr int ACHUNK = MTILE * APITCH;           // 18432
constexpr int NSTAGE = 4;                        // 2 stages x 2 K-groups
constexpr int SM_Z  = SM_A;                      // two z buffers alias A stages
constexpr int ZBYTES = MTILE * ZPITCH * 4;       // 34816
constexpr int SMEM_TOTAL = SM_A + NSTAGE * ACHUNK;  // 205824

// ---------------- persistent device state ----------------
__device__ __half g_Wf[(size_t)G4 * HID];        // 8 MB, permuted fp16 weights
__device__ float  g_P[(size_t)10 * G4];          // permuted xproj table
__device__ __half g_hf[2][(size_t)BATCH * HID];  // h double buffer (fp16)
__device__ int    g_x[BATCH * SEQ];              // canonical int32 tokens
__device__ unsigned g_bar;

// ---------------- helpers ----------------
__device__ __forceinline__ uint32_t smem_u32(const void* p) {
    uint32_t a;
    asm("{ .reg .u64 t; cvta.to.shared.u64 t, %1; cvt.u32.u64 %0, t; }" : "=r"(a) : "l"(p));
    return a;
}
__device__ __forceinline__ void cp16(uint32_t dst, const void* src) {
    asm volatile("cp.async.cg.shared.global [%0], [%1], 16;" :: "r"(dst), "l"(src));
}
__device__ __forceinline__ void ldm_x4(uint32_t* r, uint32_t addr) {
    asm volatile("ldmatrix.sync.aligned.m8n8.x4.shared.b16 {%0,%1,%2,%3}, [%4];"
        : "=r"(r[0]), "=r"(r[1]), "=r"(r[2]), "=r"(r[3]) : "r"(addr));
}
__device__ __forceinline__ void ldm_x2(uint32_t* r, uint32_t addr) {
    asm volatile("ldmatrix.sync.aligned.m8n8.x2.shared.b16 {%0,%1}, [%2];"
        : "=r"(r[0]), "=r"(r[1]) : "r"(addr));
}
__device__ __forceinline__ void mma_f16(float* d, const uint32_t* a, const uint32_t* b) {
    asm volatile("mma.sync.aligned.m16n8k16.row.col.f32.f16.f16.f32 "
        "{%0,%1,%2,%3}, {%4,%5,%6,%7}, {%8,%9}, {%0,%1,%2,%3};"
        : "+f"(d[0]), "+f"(d[1]), "+f"(d[2]), "+f"(d[3])
        : "r"(a[0]), "r"(a[1]), "r"(a[2]), "r"(a[3]), "r"(b[0]), "r"(b[1]));
}
__device__ __forceinline__ float sigf(float x) { return __fdividef(1.0f, 1.0f + __expf(-x)); }
__device__ __forceinline__ float tanhf_(float x) { return 2.0f * sigf(2.0f * x) - 1.0f; }

// ---------------- prep kernels ----------------
__global__ void zero_kernel() {
    int i = blockIdx.x * blockDim.x + threadIdx.x;
    if (i < BATCH * HID) g_hf[0][i] = __float2half(0.0f);
    if (i == 0) g_bar = 0u;
}

// Detect whether x is int64 or int32 and canonicalize to g_x (int32).
__global__ void detect_convert_x(const void* xs) {
    __shared__ unsigned acc[256];
    const unsigned* w = (const unsigned*)xs;
    unsigned o = 0;
    for (int i = threadIdx.x; i < BATCH * SEQ / 2; i += 256) o |= w[2 * i + 1];
    acc[threadIdx.x] = o;
    __syncthreads();
    for (int s = 128; s > 0; s >>= 1) {
        if (threadIdx.x < s) acc[threadIdx.x] |= acc[threadIdx.x + s];
        __syncthreads();
    }
    if (acc[0] == 0u) {   // int64 layout
        const long long* p = (const long long*)xs;
        for (int i = threadIdx.x; i < BATCH * SEQ; i += 256) g_x[i] = (int)p[i];
    } else {              // int32 layout
        const int* p = (const int*)xs;
        for (int i = threadIdx.x; i < BATCH * SEQ; i += 256) g_x[i] = p[i];
    }
}

// column n -> (gate = (n%64)/16, j = (n/64)*16 + n%16)
__global__ void prep_kernel(const float* __restrict__ Wgx, const float* __restrict__ Wix,
                            const float* __restrict__ Wfx, const float* __restrict__ Wox,
                            const float* __restrict__ Wgh, const float* __restrict__ Wih,
                            const float* __restrict__ Wfh, const float* __restrict__ Woh,
                            const float* __restrict__ embed,
                            const float* __restrict__ bg, const float* __restrict__ bi,
                            const float* __restrict__ bf_, const float* __restrict__ bo) {
    int n = blockIdx.x;
    int within = n & 63;
    int gate = within >> 4;
    int j = ((n >> 6) << 4) + (within & 15);

    const float* Wh = gate == 0 ? Wgh : gate == 1 ? Wih : gate == 2 ? Wfh : Woh;
    const float* src = Wh + (size_t)j * HID;
    __half* d = g_Wf + (size_t)n * HID;
    for (int k = threadIdx.x; k < HID; k += blockDim.x)
        d[k] = __float2half(src[k]);

    if (threadIdx.x < 10) {
        int v = threadIdx.x;
        const float* Wx = gate == 0 ? Wgx : gate == 1 ? Wix : gate == 2 ? Wfx : Wox;
        const float* bb = gate == 0 ? bg : gate == 1 ? bi : gate == 2 ? bf_ : bo;
        float s = bb[j];
#pragma unroll
        for (int e = 0; e < 10; e++) s += Wx[j * 10 + e] * embed[v * 10 + e];
        g_P[(size_t)v * G4 + n] = s;
    }
}

// ---------------- persistent LSTM kernel ----------------
__global__ __launch_bounds__(THREADS, 1) void lstm_persist() {
    extern __shared__ char sm[];
    uint32_t sb = smem_u32(sm);
    int tid = threadIdx.x;
    int lane = tid & 31, wid = tid >> 5;
    int wm = wid & 3;                 // 4 M groups (32 rows each)
    int wn = (wid >> 2) & 1;          // 2 N groups (32 cols each)
    int wk = wid >> 3;                // 2 K groups (8 chunks each)
    int ntile = blockIdx.x;           // 0..63
    int m0 = blockIdx.y * MTILE;      // 0 or 128
    int n0 = ntile * NTILE;

    // ---- load W (fp16, full K) into SMEM once: 64 rows x 2048B ----
    for (int i = tid; i < NTILE * 128; i += THREADS) {
        int r = i >> 7, s16 = i & 127;
        cp16(sb + SM_W + r * WPITCH + s16 * 16,
             g_Wf + (size_t)(n0 + r) * HID + s16 * 8);
    }
    asm volatile("cp.async.commit_group;" ::: "memory");
    asm volatile("cp.async.wait_group 0;" ::: "memory");
    __syncthreads();

    // epilogue ownership: thread -> (b_local = tid/4, 4 j's)
    int b_local = tid >> 2;
    int jb = (tid & 3) * 4;
    int b_g = m0 + b_local;
    float creg[4];
#pragma unroll
    for (int q = 0; q < 4; q++) creg[q] = 0.0f;

    // ldmatrix lane address components (validated)
    int a_row_l = (lane & 7) + ((lane >> 3) & 1) * 8;
    int a_k_l = ((lane >> 4) & 1) * 16;
    int l2 = lane & 15;
    int b_row_l = l2 & 7;
    int b_k_l = (l2 >> 3) * 16;

    float* zb0 = (float*)(sm + SM_Z);
    float* zb1 = (float*)(sm + SM_Z + ZBYTES);
    float* zbw = wk == 0 ? zb0 : zb1;

    for (int t = 0; t < SEQ; t++) {
        const __half* hg = g_hf[t & 1] + (size_t)m0 * HID;

        float acc[2][4][4];
#pragma unroll
        for (int mf = 0; mf < 2; mf++)
#pragma unroll
            for (int nf = 0; nf < 4; nf++)
#pragma unroll
                for (int e = 0; e < 4; e++) acc[mf][nf][e] = 0.0f;

        // load chunk pair i: chunk i -> stage (i&1), chunk 8+i -> stage 2+(i&1)
        auto load_pair = [&](int i) {
            uint32_t d0 = sb + SM_A + (i & 1) * ACHUNK;
            uint32_t d1 = sb + SM_A + (2 + (i & 1)) * ACHUNK;
            const __half* s0 = hg + i * KCE;
            const __half* s1 = hg + (8 + i) * KCE;
#pragma unroll
            for (int q = 0; q < 2; q++) {
                int idx = tid + (q << 9);
                int r = idx >> 3, c16 = idx & 7;
                cp16(d0 + r * APITCH + c16 * 16, s0 + (size_t)r * HID + c16 * 8);
                cp16(d1 + r * APITCH + c16 * 16, s1 + (size_t)r * HID + c16 * 8);
            }
            asm volatile("cp.async.commit_group;" ::: "memory");
        };

        load_pair(0);

        for (int i = 0; i < 8; i++) {
            asm volatile("cp.async.wait_group 0;" ::: "memory");
            __syncthreads();              // pair i visible; pair i-1 fully consumed
            if (i < 7) load_pair(i + 1);  // writes stages consumed at i-1

            int kc = wk * 8 + i;
            uint32_t As = sb + SM_A + (uint32_t)((wk * 2 + (i & 1)) * ACHUNK);
#pragma unroll
            for (int ks = 0; ks < 4; ks++) {
                uint32_t Af[2][4], Bf[4][2];
                int kba = ks * 32;
                int kbw = kc * 128 + ks * 32;
#pragma unroll
                for (int mf = 0; mf < 2; mf++)
                    ldm_x4(Af[mf], As + (uint32_t)((wm * 32 + mf * 16 + a_row_l) * APITCH + kba + a_k_l));
#pragma unroll
                for (int nf = 0; nf < 4; nf++)
                    ldm_x2(Bf[nf], sb + SM_W + (uint32_t)((wn * 32 + nf * 8 + b_row_l) * WPITCH + kbw + b_k_l));
#pragma unroll
                for (int mf = 0; mf < 2; mf++)
#pragma unroll
                    for (int nf = 0; nf < 4; nf++)
                        mma_f16(acc[mf][nf], Af[mf], Bf[nf]);
            }
        }
        __syncthreads();   // all consumption done before z aliases the stages

        // ---- write partial z (per K-group buffer) ----
        {
            int r0 = (lane >> 2), c0 = (lane & 3) * 2;
#pragma unroll
            for (int mf = 0; mf < 2; mf++)
#pragma unroll
                for (int nf = 0; nf < 4; nf++) {
                    int row = wm * 32 + mf * 16 + r0;
                    int col = wn * 32 + nf * 8 + c0;
                    zbw[row * ZPITCH + col]           = acc[mf][nf][0];
                    zbw[row * ZPITCH + col + 1]       = acc[mf][nf][1];
                    zbw[(row + 8) * ZPITCH + col]     = acc[mf][nf][2];
                    zbw[(row + 8) * ZPITCH + col + 1] = acc[mf][nf][3];
                }
        }
        __syncthreads();

        // ---- epilogue: z = zb0 + zb1 + P; gates; c/h update ----
        {
            int v = g_x[b_g * SEQ + t];
            const float* Pr = g_P + (size_t)v * G4 + n0;
            const float* z0 = zb0 + b_local * ZPITCH;
            const float* z1 = zb1 + b_local * ZPITCH;
            __half hh[4];
#pragma unroll
            for (int jj = 0; jj < 4; jj++) {
                int j = jb + jj;
                float zg = z0[j]      + z1[j]      + Pr[j];
                float zi = z0[16 + j] + z1[16 + j] + Pr[16 + j];
                float zf = z0[32 + j] + z1[32 + j] + Pr[32 + j];
                float zo = z0[48 + j] + z1[48 + j] + Pr[48 + j];
                float g  = tanhf_(zg);
                float ig = sigf(zi);
                float fg = sigf(zf);
                float og = sigf(zo);
                float cn = g * ig + creg[jj] * fg;
                creg[jj] = cn;
                hh[jj] = __float2half(tanhf_(cn) * og);
            }
            size_t ho = (size_t)b_g * HID + ntile * 16 + jb;
            *(uint2*)(g_hf[(t + 1) & 1] + ho) = *(const uint2*)hh;
        }

        // ---- grid barrier ----
        __threadfence();
        __syncthreads();
        if (tid == 0) {
            atomicAdd(&g_bar, 1u);
            unsigned tgt = 128u * (unsigned)(t + 1);
            unsigned vv;
            do {
                asm volatile("ld.acquire.gpu.u32 %0, [%1];" : "=r"(vv) : "l"(&g_bar));
            } while (vv < tgt);
        }
        __syncthreads();
    }
}

// ---------------- final projection ----------------
__global__ void final_proj_kernel(const float* __restrict__ Wp, const float* __restrict__ bp,
                                  float* __restrict__ out) {
    int b = blockIdx.x;
    int tid = threadIdx.x;   // 128
    const __half* h = g_hf[0] + (size_t)b * HID;   // after 256 steps, h in buf 0
    float acc[10];
#pragma unroll
    for (int c = 0; c < 10; c++) acc[c] = 0.0f;
    for (int k = tid; k < HID; k += 128) {
        float hv = __half2float(h[k]);
#pragma unroll
        for (int c = 0; c < 10; c++) acc[c] += hv * Wp[c * HID + k];
    }
#pragma unroll
    for (int c = 0; c < 10; c++)
#pragma unroll
        for (int off = 16; off > 0; off >>= 1)
            acc[c] += __shfl_xor_sync(0xffffffffu, acc[c], off);
    __shared__ float red[4][10];
    int wid = tid >> 5, lid = tid & 31;
    if (lid == 0) {
#pragma unroll
        for (int c = 0; c < 10; c++) red[wid][c] = acc[c];
    }
    __syncthreads();
    if (tid < 10)
        out[b * 10 + tid] = red[0][tid] + red[1][tid] + red[2][tid] + red[3][tid] + bp[tid];
}

// ---------------- launch ----------------
extern "C" void kernel_launch(void* const* d_in, const int* in_sizes, int n_in,
                              void* d_out, int out_size) {
    const void*  x   = d_in[0];
    const float* embed = (const float*)d_in[1];
    const float* Wgx = (const float*)d_in[2];
    const float* Wix = (const float*)d_in[3];
    const float* Wfx = (const float*)d_in[4];
    const float* Wox = (const float*)d_in[5];
    const float* Wgh = (const float*)d_in[6];
    const float* Wih = (const float*)d_in[7];
    const float* Wfh = (const float*)d_in[8];
    const float* Woh = (const float*)d_in[9];
    const float* Wph = (const float*)d_in[10];
    const float* bg  = (const float*)d_in[11];
    const float* bi  = (const float*)d_in[12];
    const float* bf_ = (const float*)d_in[13];
    const float* bo  = (const float*)d_in[14];
    const float* bp  = (const float*)d_in[15];

    cudaFuncSetAttribute(lstm_persist, cudaFuncAttributeMaxDynamicSharedMemorySize, SMEM_TOTAL);

    zero_kernel<<<(BATCH * HID + 255) / 256, 256>>>();
    detect_convert_x<<<1, 256>>>(x);
    prep_kernel<<<G4, 128>>>(Wgx, Wix, Wfx, Wox, Wgh, Wih, Wfh, Woh, embed, bg, bi, bf_, bo);

    dim3 grid(G4 / NTILE, BATCH / MTILE);   // (64, 2) = 128 CTAs, all resident
    lstm_persist<<<grid, THREADS, SMEM_TOTAL>>>();

    final_proj_kernel<<<BATCH, 128>>>(Wph, bp, (float*)d_out);
}

// round 8
// speedup vs baseline: 5.4029x; 1.0841x over previous
#include <cuda_runtime.h>
#include <cuda_fp16.h>
#include <cstdint>
#include <cstring>

// ============================================================
// LSTM on GB300, base-target ISA (no tcgen05 available).
// R7: stall attack on the R6 winner.
//  - P-table slice cached in SMEM (epilogue LDG -> LDS.128)
//  - g_x token load hoisted to step start
//  - grid barrier split per m-half (2 x 64 CTAs)
//  - ks-pair fragment prefetch; B loads via ldmatrix.x4
//  - 512 threads/CTA, warps 4M x 2N x 2K (K-split)
//  - ONE persistent kernel, all 256 steps; W in SMEM; c in regs.
// ============================================================

constexpr int BATCH = 256;
constexpr int SEQ   = 256;
constexpr int HID   = 1024;
constexpr int G4    = 4096;
constexpr int NTILE = 64;
constexpr int MTILE = 128;
constexpr int KCE   = 64;             // K elems (fp16) per chunk = 128 bytes
constexpr int WPITCH = 2064;          // 2048 + 16 (conflict-free ldmatrix)
constexpr int APITCH = 144;           // 128 + 16
constexpr int ZPITCH = 68;            // floats
constexpr int THREADS = 512;

constexpr int SM_W  = 0;
constexpr int SM_A  = NTILE * WPITCH;            // 132096
constexpr int ACHUNK = MTILE * APITCH;           // 18432
constexpr int NSTAGE = 4;                        // 2 stages x 2 K-groups
constexpr int SM_Z  = SM_A;                      // two z buffers alias A stages
constexpr int ZBYTES = MTILE * ZPITCH * 4;       // 34816
constexpr int SM_P  = SM_A + NSTAGE * ACHUNK;    // 205824
constexpr int SMEM_TOTAL = SM_P + 10 * NTILE * 4;   // 208384

// ---------------- persistent device state ----------------
__device__ __half g_Wf[(size_t)G4 * HID];        // 8 MB, permuted fp16 weights
__device__ float  g_P[(size_t)10 * G4];          // permuted xproj table
__device__ __half g_hf[2][(size_t)BATCH * HID];  // h double buffer (fp16)
__device__ int    g_x[BATCH * SEQ];              // canonical int32 tokens
__device__ unsigned g_bar2[2];                   // per-m-half barriers

// ---------------- helpers ----------------
__device__ __forceinline__ uint32_t smem_u32(const void* p) {
    uint32_t a;
    asm("{ .reg .u64 t; cvta.to.shared.u64 t, %1; cvt.u32.u64 %0, t; }" : "=r"(a) : "l"(p));
    return a;
}
__device__ __forceinline__ void cp16(uint32_t dst, const void* src) {
    asm volatile("cp.async.cg.shared.global [%0], [%1], 16;" :: "r"(dst), "l"(src));
}
__device__ __forceinline__ void ldm_x4(uint32_t* r, uint32_t addr) {
    asm volatile("ldmatrix.sync.aligned.m8n8.x4.shared.b16 {%0,%1,%2,%3}, [%4];"
        : "=r"(r[0]), "=r"(r[1]), "=r"(r[2]), "=r"(r[3]) : "r"(addr));
}
__device__ __forceinline__ void mma_f16(float* d, const uint32_t* a, const uint32_t* b) {
    asm volatile("mma.sync.aligned.m16n8k16.row.col.f32.f16.f16.f32 "
        "{%0,%1,%2,%3}, {%4,%5,%6,%7}, {%8,%9}, {%0,%1,%2,%3};"
        : "+f"(d[0]), "+f"(d[1]), "+f"(d[2]), "+f"(d[3])
        : "r"(a[0]), "r"(a[1]), "r"(a[2]), "r"(a[3]), "r"(b[0]), "r"(b[1]));
}
__device__ __forceinline__ float sigf(float x) { return __fdividef(1.0f, 1.0f + __expf(-x)); }
__device__ __forceinline__ float tanhf_(float x) { return 2.0f * sigf(2.0f * x) - 1.0f; }

// ---------------- prep kernels ----------------
__global__ void zero_kernel() {
    int i = blockIdx.x * blockDim.x + threadIdx.x;
    if (i < BATCH * HID) g_hf[0][i] = __float2half(0.0f);
    if (i == 0) { g_bar2[0] = 0u; g_bar2[1] = 0u; }
}

// Detect whether x is int64 or int32 and canonicalize to g_x (int32).
__global__ void detect_convert_x(const void* xs) {
    __shared__ unsigned acc[256];
    const unsigned* w = (const unsigned*)xs;
    unsigned o = 0;
    for (int i = threadIdx.x; i < BATCH * SEQ / 2; i += 256) o |= w[2 * i + 1];
    acc[threadIdx.x] = o;
    __syncthreads();
    for (int s = 128; s > 0; s >>= 1) {
        if (threadIdx.x < s) acc[threadIdx.x] |= acc[threadIdx.x + s];
        __syncthreads();
    }
    if (acc[0] == 0u) {   // int64 layout
        const long long* p = (const long long*)xs;
        for (int i = threadIdx.x; i < BATCH * SEQ; i += 256) g_x[i] = (int)p[i];
    } else {              // int32 layout
        const int* p = (const int*)xs;
        for (int i = threadIdx.x; i < BATCH * SEQ; i += 256) g_x[i] = p[i];
    }
}

// column n -> (gate = (n%64)/16, j = (n/64)*16 + n%16)
__global__ void prep_kernel(const float* __restrict__ Wgx, const float* __restrict__ Wix,
                            const float* __restrict__ Wfx, const float* __restrict__ Wox,
                            const float* __restrict__ Wgh, const float* __restrict__ Wih,
                            const float* __restrict__ Wfh, const float* __restrict__ Woh,
                            const float* __restrict__ embed,
                            const float* __restrict__ bg, const float* __restrict__ bi,
                            const float* __restrict__ bf_, const float* __restrict__ bo) {
    int n = blockIdx.x;
    int within = n & 63;
    int gate = within >> 4;
    int j = ((n >> 6) << 4) + (within & 15);

    const float* Wh = gate == 0 ? Wgh : gate == 1 ? Wih : gate == 2 ? Wfh : Woh;
    const float* src = Wh + (size_t)j * HID;
    __half* d = g_Wf + (size_t)n * HID;
    for (int k = threadIdx.x; k < HID; k += blockDim.x)
        d[k] = __float2half(src[k]);

    if (threadIdx.x < 10) {
        int v = threadIdx.x;
        const float* Wx = gate == 0 ? Wgx : gate == 1 ? Wix : gate == 2 ? Wfx : Wox;
        const float* bb = gate == 0 ? bg : gate == 1 ? bi : gate == 2 ? bf_ : bo;
        float s = bb[j];
#pragma unroll
        for (int e = 0; e < 10; e++) s += Wx[j * 10 + e] * embed[v * 10 + e];
        g_P[(size_t)v * G4 + n] = s;
    }
}

// ---------------- persistent LSTM kernel ----------------
__global__ __launch_bounds__(THREADS, 1) void lstm_persist() {
    extern __shared__ char sm[];
    uint32_t sb = smem_u32(sm);
    int tid = threadIdx.x;
    int lane = tid & 31, wid = tid >> 5;
    int wm = wid & 3;                 // 4 M groups (32 rows each)
    int wn = (wid >> 2) & 1;          // 2 N groups (32 cols each)
    int wk = wid >> 3;                // 2 K groups (8 chunks each)
    int ntile = blockIdx.x;           // 0..63
    int my = blockIdx.y;
    int m0 = my * MTILE;              // 0 or 128
    int n0 = ntile * NTILE;

    // ---- load W (fp16, full K) into SMEM once: 64 rows x 2048B ----
    for (int i = tid; i < NTILE * 128; i += THREADS) {
        int r = i >> 7, s16 = i & 127;
        cp16(sb + SM_W + r * WPITCH + s16 * 16,
             g_Wf + (size_t)(n0 + r) * HID + s16 * 8);
    }
    asm volatile("cp.async.commit_group;" ::: "memory");
    // ---- load P slice (10 x 64 floats) into SMEM once ----
    float* sp = (float*)(sm + SM_P);
    for (int i = tid; i < 10 * NTILE; i += THREADS)
        sp[i] = g_P[(size_t)(i >> 6) * G4 + n0 + (i & 63)];
    asm volatile("cp.async.wait_group 0;" ::: "memory");
    __syncthreads();

    // epilogue ownership: thread -> (b_local = tid/4, 4 j's)
    int b_local = tid >> 2;
    int jb = (tid & 3) * 4;
    int b_g = m0 + b_local;
    float creg[4];
#pragma unroll
    for (int q = 0; q < 4; q++) creg[q] = 0.0f;

    // A ldmatrix lane mapping (validated)
    int a_row_l = (lane & 7) + ((lane >> 3) & 1) * 8;
    int a_k_l = ((lane >> 4) & 1) * 16;
    // B ldmatrix.x4 lane mapping: matrix m = (nf_off = m>>1, kh = m&1)
    int bm = lane >> 3, br = lane & 7;
    uint32_t b_lane_off = (uint32_t)((wn * 32 + (bm >> 1) * 8 + br) * WPITCH + (bm & 1) * 16);

    float* zb0 = (float*)(sm + SM_Z);
    float* zb1 = (float*)(sm + SM_Z + ZBYTES);
    float* zbw = wk == 0 ? zb0 : zb1;

    for (int t = 0; t < SEQ; t++) {
        const __half* hg = g_hf[t & 1] + (size_t)m0 * HID;
        int v = g_x[b_g * SEQ + t];          // hoisted: latency hidden by GEMM

        float acc[2][4][4];
#pragma unroll
        for (int mf = 0; mf < 2; mf++)
#pragma unroll
            for (int nf = 0; nf < 4; nf++)
#pragma unroll
                for (int e = 0; e < 4; e++) acc[mf][nf][e] = 0.0f;

        // load chunk pair i: chunk i -> stage (i&1), chunk 8+i -> stage 2+(i&1)
        auto load_pair = [&](int i) {
            uint32_t d0 = sb + SM_A + (i & 1) * ACHUNK;
            uint32_t d1 = sb + SM_A + (2 + (i & 1)) * ACHUNK;
            const __half* s0 = hg + i * KCE;
            const __half* s1 = hg + (8 + i) * KCE;
#pragma unroll
            for (int q = 0; q < 2; q++) {
                int idx = tid + (q << 9);
                int r = idx >> 3, c16 = idx & 7;
                cp16(d0 + r * APITCH + c16 * 16, s0 + (size_t)r * HID + c16 * 8);
                cp16(d1 + r * APITCH + c16 * 16, s1 + (size_t)r * HID + c16 * 8);
            }
            asm volatile("cp.async.commit_group;" ::: "memory");
        };

        load_pair(0);

        for (int i = 0; i < 8; i++) {
            asm volatile("cp.async.wait_group 0;" ::: "memory");
            __syncthreads();              // pair i visible; pair i-1 fully consumed
            if (i < 7) load_pair(i + 1);  // writes stages consumed at i-1

            int kc = wk * 8 + i;
            uint32_t As = sb + SM_A + (uint32_t)((wk * 2 + (i & 1)) * ACHUNK);
            uint32_t Arow0 = As + (uint32_t)((wm * 32 + a_row_l) * APITCH + a_k_l);
            uint32_t Brow  = sb + SM_W + b_lane_off + (uint32_t)(kc * 128);
#pragma unroll
            for (int ksp = 0; ksp < 2; ksp++) {
                uint32_t Af[2][2][4];     // [kq][mf][4]
                uint32_t Bf[2][4][2];     // [kq][nf][2]
#pragma unroll
                for (int kq = 0; kq < 2; kq++) {
                    int ks = ksp * 2 + kq;
                    int kba = ks * 32;
                    ldm_x4(Af[kq][0], Arow0 + kba);
                    ldm_x4(Af[kq][1], Arow0 + 16 * APITCH + kba);
                    ldm_x4(&Bf[kq][0][0], Brow + kba);                 // nf 0,1
                    ldm_x4(&Bf[kq][2][0], Brow + 16 * WPITCH + kba);   // nf 2,3
                }
#pragma unroll
                for (int kq = 0; kq < 2; kq++)
#pragma unroll
                    for (int mf = 0; mf < 2; mf++)
#pragma unroll
                        for (int nf = 0; nf < 4; nf++)
                            mma_f16(acc[mf][nf], Af[kq][mf], Bf[kq][nf]);
            }
        }
        __syncthreads();   // all consumption done before z aliases the stages

        // ---- write partial z (per K-group buffer) ----
        {
            int r0 = (lane >> 2), c0 = (lane & 3) * 2;
#pragma unroll
            for (int mf = 0; mf < 2; mf++)
#pragma unroll
                for (int nf = 0; nf < 4; nf++) {
                    int row = wm * 32 + mf * 16 + r0;
                    int col = wn * 32 + nf * 8 + c0;
                    zbw[row * ZPITCH + col]           = acc[mf][nf][0];
                    zbw[row * ZPITCH + col + 1]       = acc[mf][nf][1];
                    zbw[(row + 8) * ZPITCH + col]     = acc[mf][nf][2];
                    zbw[(row + 8) * ZPITCH + col + 1] = acc[mf][nf][3];
                }
        }
        __syncthreads();

        // ---- epilogue: z = zb0 + zb1 + P; gates; c/h update (float4 LDS) ----
        {
            const float* Pr = sp + v * NTILE;
            const float* z0 = zb0 + b_local * ZPITCH;
            const float* z1 = zb1 + b_local * ZPITCH;
            union F4 { float4 v; float f[4]; };
            F4 zg, zi, zf, zo;
            {
                float4 a, b, p;
                a = *(const float4*)(z0 + jb);      b = *(const float4*)(z1 + jb);      p = *(const float4*)(Pr + jb);
                zg.v = make_float4(a.x + b.x + p.x, a.y + b.y + p.y, a.z + b.z + p.z, a.w + b.w + p.w);
                a = *(const float4*)(z0 + 16 + jb); b = *(const float4*)(z1 + 16 + jb); p = *(const float4*)(Pr + 16 + jb);
                zi.v = make_float4(a.x + b.x + p.x, a.y + b.y + p.y, a.z + b.z + p.z, a.w + b.w + p.w);
                a = *(const float4*)(z0 + 32 + jb); b = *(const float4*)(z1 + 32 + jb); p = *(const float4*)(Pr + 32 + jb);
                zf.v = make_float4(a.x + b.x + p.x, a.y + b.y + p.y, a.z + b.z + p.z, a.w + b.w + p.w);
                a = *(const float4*)(z0 + 48 + jb); b = *(const float4*)(z1 + 48 + jb); p = *(const float4*)(Pr + 48 + jb);
                zo.v = make_float4(a.x + b.x + p.x, a.y + b.y + p.y, a.z + b.z + p.z, a.w + b.w + p.w);
            }
            __half hh[4];
#pragma unroll
            for (int jj = 0; jj < 4; jj++) {
                float g  = tanhf_(zg.f[jj]);
                float ig = sigf(zi.f[jj]);
                float fg = sigf(zf.f[jj]);
                float og = sigf(zo.f[jj]);
                float cn = g * ig + creg[jj] * fg;
                creg[jj] = cn;
                hh[jj] = __float2half(tanhf_(cn) * og);
            }
            size_t ho = (size_t)b_g * HID + ntile * 16 + jb;
            *(uint2*)(g_hf[(t + 1) & 1] + ho) = *(const uint2*)hh;
        }

        // ---- grid barrier (per m-half: 64 CTAs each) ----
        __threadfence();
        __syncthreads();
        if (tid == 0) {
            atomicAdd(&g_bar2[my], 1u);
            unsigned tgt = 64u * (unsigned)(t + 1);
            unsigned vv;
            do {
                asm volatile("ld.acquire.gpu.u32 %0, [%1];" : "=r"(vv) : "l"(&g_bar2[my]));
            } while (vv < tgt);
        }
        __syncthreads();
    }
}

// ---------------- final projection ----------------
__global__ void final_proj_kernel(const float* __restrict__ Wp, const float* __restrict__ bp,
                                  float* __restrict__ out) {
    int b = blockIdx.x;
    int tid = threadIdx.x;   // 128
    const __half* h = g_hf[0] + (size_t)b * HID;   // after 256 steps, h in buf 0
    float acc[10];
#pragma unroll
    for (int c = 0; c < 10; c++) acc[c] = 0.0f;
    for (int k = tid; k < HID; k += 128) {
        float hv = __half2float(h[k]);
#pragma unroll
        for (int c = 0; c < 10; c++) acc[c] += hv * Wp[c * HID + k];
    }
#pragma unroll
    for (int c = 0; c < 10; c++)
#pragma unroll
        for (int off = 16; off > 0; off >>= 1)
            acc[c] += __shfl_xor_sync(0xffffffffu, acc[c], off);
    __shared__ float red[4][10];
    int wid = tid >> 5, lid = tid & 31;
    if (lid == 0) {
#pragma unroll
        for (int c = 0; c < 10; c++) red[wid][c] = acc[c];
    }
    __syncthreads();
    if (tid < 10)
        out[b * 10 + tid] = red[0][tid] + red[1][tid] + red[2][tid] + red[3][tid] + bp[tid];
}

// ---------------- launch ----------------
extern "C" void kernel_launch(void* const* d_in, const int* in_sizes, int n_in,
                              void* d_out, int out_size) {
    const void*  x   = d_in[0];
    const float* embed = (const float*)d_in[1];
    const float* Wgx = (const float*)d_in[2];
    const float* Wix = (const float*)d_in[3];
    const float* Wfx = (const float*)d_in[4];
    const float* Wox = (const float*)d_in[5];
    const float* Wgh = (const float*)d_in[6];
    const float* Wih = (const float*)d_in[7];
    const float* Wfh = (const float*)d_in[8];
    const float* Woh = (const float*)d_in[9];
    const float* Wph = (const float*)d_in[10];
    const float* bg  = (const float*)d_in[11];
    const float* bi  = (const float*)d_in[12];
    const float* bf_ = (const float*)d_in[13];
    const float* bo  = (const float*)d_in[14];
    const float* bp  = (const float*)d_in[15];

    cudaFuncSetAttribute(lstm_persist, cudaFuncAttributeMaxDynamicSharedMemorySize, SMEM_TOTAL);

    zero_kernel<<<(BATCH * HID + 255) / 256, 256>>>();
    detect_convert_x<<<1, 256>>>(x);
    prep_kernel<<<G4, 128>>>(Wgx, Wix, Wfx, Wox, Wgh, Wih, Wfh, Woh, embed, bg, bi, bf_, bo);

    dim3 grid(G4 / NTILE, BATCH / MTILE);   // (64, 2) = 128 CTAs, all resident
    lstm_persist<<<grid, THREADS, SMEM_TOTAL>>>();

    final_proj_kernel<<<BATCH, 128>>>(Wph, bp, (float*)d_out);
}

// round 9
// speedup vs baseline: 6.2126x; 1.1499x over previous
#include <cuda_runtime.h>
#include <cuda_fp16.h>
#include <cstdint>
#include <cstring>

// ============================================================
// LSTM on GB300, base-target ISA (no tcgen05 available).
// R9: depth-2 cp.async pipeline (3 stages per K-group) funded by
// XOR-swizzled SMEM (no row padding); release-atomic barrier.
//  - 512 threads/CTA, warps 4M x 2N x 2K (K-split)
//  - ONE persistent kernel, all 256 steps; W in SMEM; c in regs;
//    per-m-half grid barrier (64 CTAs each).
//  - P-table slice in SMEM; hoisted token load; float4 epilogue.
// ============================================================

constexpr int BATCH = 256;
constexpr int SEQ   = 256;
constexpr int HID   = 1024;
constexpr int G4    = 4096;
constexpr int NTILE = 64;
constexpr int MTILE = 128;
constexpr int KCE   = 64;             // K elems (fp16) per chunk = 128 bytes
constexpr int WPITCH = 2048;          // swizzled, no pad
constexpr int APITCH = 128;           // swizzled, no pad
constexpr int ZPITCH = 68;            // floats
constexpr int THREADS = 512;

constexpr int SM_W  = 0;
constexpr int SM_A  = NTILE * WPITCH;            // 131072
constexpr int ACHUNK = MTILE * APITCH;           // 16384
constexpr int NSTAGE = 6;                        // 3 stages x 2 K-groups
constexpr int SM_Z  = SM_A;                      // two z buffers alias A stages
constexpr int ZBYTES = MTILE * ZPITCH * 4;       // 34816 (x2 <= 6*16KB ok)
constexpr int SM_P  = SM_A + NSTAGE * ACHUNK;    // 229376
constexpr int SMEM_TOTAL = SM_P + 10 * NTILE * 4;   // 231936 (<= 232448)

// ---------------- persistent device state ----------------
__device__ __half g_Wf[(size_t)G4 * HID];        // 8 MB, permuted fp16 weights
__device__ float  g_P[(size_t)10 * G4];          // permuted xproj table
__device__ __half g_hf[2][(size_t)BATCH * HID];  // h double buffer (fp16)
__device__ int    g_x[BATCH * SEQ];              // canonical int32 tokens
__device__ unsigned g_bar2[2];                   // per-m-half barriers

// ---------------- helpers ----------------
__device__ __forceinline__ uint32_t smem_u32(const void* p) {
    uint32_t a;
    asm("{ .reg .u64 t; cvta.to.shared.u64 t, %1; cvt.u32.u64 %0, t; }" : "=r"(a) : "l"(p));
    return a;
}
__device__ __forceinline__ void cp16(uint32_t dst, const void* src) {
    asm volatile("cp.async.cg.shared.global [%0], [%1], 16;" :: "r"(dst), "l"(src));
}
__device__ __forceinline__ void ldm_x4(uint32_t* r, uint32_t addr) {
    asm volatile("ldmatrix.sync.aligned.m8n8.x4.shared.b16 {%0,%1,%2,%3}, [%4];"
        : "=r"(r[0]), "=r"(r[1]), "=r"(r[2]), "=r"(r[3]) : "r"(addr));
}
__device__ __forceinline__ void mma_f16(float* d, const uint32_t* a, const uint32_t* b) {
    asm volatile("mma.sync.aligned.m16n8k16.row.col.f32.f16.f16.f32 "
        "{%0,%1,%2,%3}, {%4,%5,%6,%7}, {%8,%9}, {%0,%1,%2,%3};"
        : "+f"(d[0]), "+f"(d[1]), "+f"(d[2]), "+f"(d[3])
        : "r"(a[0]), "r"(a[1]), "r"(a[2]), "r"(a[3]), "r"(b[0]), "r"(b[1]));
}
__device__ __forceinline__ float sigf(float x) { return __fdividef(1.0f, 1.0f + __expf(-x)); }
__device__ __forceinline__ float tanhf_(float x) { return 2.0f * sigf(2.0f * x) - 1.0f; }

// ---------------- prep kernels ----------------
__global__ void zero_kernel() {
    int i = blockIdx.x * blockDim.x + threadIdx.x;
    if (i < BATCH * HID) g_hf[0][i] = __float2half(0.0f);
    if (i == 0) { g_bar2[0] = 0u; g_bar2[1] = 0u; }
}

// Detect whether x is int64 or int32 and canonicalize to g_x (int32).
__global__ void detect_convert_x(const void* xs) {
    __shared__ unsigned acc[256];
    const unsigned* w = (const unsigned*)xs;
    unsigned o = 0;
    for (int i = threadIdx.x; i < BATCH * SEQ / 2; i += 256) o |= w[2 * i + 1];
    acc[threadIdx.x] = o;
    __syncthreads();
    for (int s = 128; s > 0; s >>= 1) {
        if (threadIdx.x < s) acc[threadIdx.x] |= acc[threadIdx.x + s];
        __syncthreads();
    }
    if (acc[0] == 0u) {   // int64 layout
        const long long* p = (const long long*)xs;
        for (int i = threadIdx.x; i < BATCH * SEQ; i += 256) g_x[i] = (int)p[i];
    } else {              // int32 layout
        const int* p = (const int*)xs;
        for (int i = threadIdx.x; i < BATCH * SEQ; i += 256) g_x[i] = p[i];
    }
}

// column n -> (gate = (n%64)/16, j = (n/64)*16 + n%16)
__global__ void prep_kernel(const float* __restrict__ Wgx, const float* __restrict__ Wix,
                            const float* __restrict__ Wfx, const float* __restrict__ Wox,
                            const float* __restrict__ Wgh, const float* __restrict__ Wih,
                            const float* __restrict__ Wfh, const float* __restrict__ Woh,
                            const float* __restrict__ embed,
                            const float* __restrict__ bg, const float* __restrict__ bi,
                            const float* __restrict__ bf_, const float* __restrict__ bo) {
    int n = blockIdx.x;
    int within = n & 63;
    int gate = within >> 4;
    int j = ((n >> 6) << 4) + (within & 15);

    const float* Wh = gate == 0 ? Wgh : gate == 1 ? Wih : gate == 2 ? Wfh : Woh;
    const float* src = Wh + (size_t)j * HID;
    __half* d = g_Wf + (size_t)n * HID;
    for (int k = threadIdx.x; k < HID; k += blockDim.x)
        d[k] = __float2half(src[k]);

    if (threadIdx.x < 10) {
        int v = threadIdx.x;
        const float* Wx = gate == 0 ? Wgx : gate == 1 ? Wix : gate == 2 ? Wfx : Wox;
        const float* bb = gate == 0 ? bg : gate == 1 ? bi : gate == 2 ? bf_ : bo;
        float s = bb[j];
#pragma unroll
        for (int e = 0; e < 10; e++) s += Wx[j * 10 + e] * embed[v * 10 + e];
        g_P[(size_t)v * G4 + n] = s;
    }
}

// ---------------- persistent LSTM kernel ----------------
__global__ __launch_bounds__(THREADS, 1) void lstm_persist() {
    extern __shared__ char sm[];
    uint32_t sb = smem_u32(sm);
    int tid = threadIdx.x;
    int lane = tid & 31, wid = tid >> 5;
    int wm = wid & 3;                 // 4 M groups (32 rows each)
    int wn = (wid >> 2) & 1;          // 2 N groups (32 cols each)
    int wk = wid >> 3;                // 2 K groups (8 chunks each)
    int ntile = blockIdx.x;           // 0..63
    int my = blockIdx.y;
    int m0 = my * MTILE;              // 0 or 128
    int n0 = ntile * NTILE;

    // ---- load W (fp16, full K, swizzled) into SMEM once ----
    for (int i = tid; i < NTILE * 128; i += THREADS) {
        int r = i >> 7, s16 = i & 127;
        uint32_t slot = (uint32_t)(s16 ^ (r & 7));
        cp16(sb + SM_W + r * WPITCH + (slot << 4),
             g_Wf + (size_t)(n0 + r) * HID + s16 * 8);
    }
    asm volatile("cp.async.commit_group;" ::: "memory");
    // ---- load P slice (10 x 64 floats) into SMEM once ----
    float* sp = (float*)(sm + SM_P);
    for (int i = tid; i < 10 * NTILE; i += THREADS)
        sp[i] = g_P[(size_t)(i >> 6) * G4 + n0 + (i & 63)];
    asm volatile("cp.async.wait_group 0;" ::: "memory");
    __syncthreads();

    // epilogue ownership: thread -> (b_local = tid/4, 4 j's)
    int b_local = tid >> 2;
    int jb = (tid & 3) * 4;
    int b_g = m0 + b_local;
    float creg[4];
#pragma unroll
    for (int q = 0; q < 4; q++) creg[q] = 0.0f;

    // A ldmatrix lane mapping (swizzled)
    int a_row_l = (lane & 7) + ((lane >> 3) & 1) * 8;
    int a_sel = lane & 7;                 // row&7 for swizzle
    int a_klane = (lane >> 4) & 1;        // 16B column selector
    // B ldmatrix.x4 lane mapping
    int bm = lane >> 3, br = lane & 7;
    int b_row = (bm >> 1) * 8 + br;       // + wn*32 (+16 for 2nd x4)
    int b_col0 = bm & 1;
    uint32_t b_base = sb + SM_W + (uint32_t)((wn * 32 + b_row) * WPITCH);

    float* zb0 = (float*)(sm + SM_Z);
    float* zb1 = (float*)(sm + SM_Z + ZBYTES);
    float* zbw = wk == 0 ? zb0 : zb1;

    for (int t = 0; t < SEQ; t++) {
        const __half* hg = g_hf[t & 1] + (size_t)m0 * HID;
        int v = g_x[b_g * SEQ + t];          // hoisted: latency hidden by GEMM

        float acc[2][4][4];
#pragma unroll
        for (int mf = 0; mf < 2; mf++)
#pragma unroll
            for (int nf = 0; nf < 4; nf++)
#pragma unroll
                for (int e = 0; e < 4; e++) acc[mf][nf][e] = 0.0f;

        // load chunk pair i into ring stage i%3 (per K-group)
        auto load_pair = [&](int i) {
            int st = i % 3;
            uint32_t d0 = sb + SM_A + st * ACHUNK;
            uint32_t d1 = sb + SM_A + (3 + st) * ACHUNK;
            const __half* s0 = hg + i * KCE;
            const __half* s1 = hg + (8 + i) * KCE;
#pragma unroll
            for (int q = 0; q < 2; q++) {
                int idx = tid + (q << 9);
                int r = idx >> 3, c16 = idx & 7;
                uint32_t so = (uint32_t)(r * APITCH + ((c16 ^ (r & 7)) << 4));
                cp16(d0 + so, s0 + (size_t)r * HID + c16 * 8);
                cp16(d1 + so, s1 + (size_t)r * HID + c16 * 8);
            }
            asm volatile("cp.async.commit_group;" ::: "memory");
        };

        load_pair(0);
        load_pair(1);

        for (int i = 0; i < 8; i++) {
            if (i < 7) asm volatile("cp.async.wait_group 1;" ::: "memory");
            else       asm volatile("cp.async.wait_group 0;" ::: "memory");
            __syncthreads();              // pair i visible; stage (i+2)%3 free
            if (i < 6) load_pair(i + 2);

            int kc = wk * 8 + i;
            uint32_t As = sb + SM_A + (uint32_t)((wk * 3 + i % 3) * ACHUNK);
            uint32_t Arow0 = As + (uint32_t)((wm * 32 + a_row_l) * APITCH);
            int b_colk = kc * 8 + b_col0;
#pragma unroll
            for (int ksp = 0; ksp < 2; ksp++) {
                uint32_t Af[2][2][4];     // [kq][mf][4]
                uint32_t Bf[2][4][2];     // [kq][nf][2]
#pragma unroll
                for (int kq = 0; kq < 2; kq++) {
                    int ks = ksp * 2 + kq;
                    uint32_t a_off = (uint32_t)(((ks * 2 + a_klane) ^ a_sel) << 4);
                    ldm_x4(Af[kq][0], Arow0 + a_off);
                    ldm_x4(Af[kq][1], Arow0 + 16 * APITCH + a_off);
                    uint32_t b_off = (uint32_t)(((b_colk + ks * 2) ^ br) << 4);
                    ldm_x4(&Bf[kq][0][0], b_base + b_off);                 // nf 0,1
                    ldm_x4(&Bf[kq][2][0], b_base + 16 * WPITCH + b_off);   // nf 2,3
                }
#pragma unroll
                for (int kq = 0; kq < 2; kq++)
#pragma unroll
                    for (int mf = 0; mf < 2; mf++)
#pragma unroll
                        for (int nf = 0; nf < 4; nf++)
                            mma_f16(acc[mf][nf], Af[kq][mf], Bf[kq][nf]);
            }
        }
        __syncthreads();   // all consumption done before z aliases the stages

        // ---- write partial z (per K-group buffer) ----
        {
            int r0 = (lane >> 2), c0 = (lane & 3) * 2;
#pragma unroll
            for (int mf = 0; mf < 2; mf++)
#pragma unroll
                for (int nf = 0; nf < 4; nf++) {
                    int row = wm * 32 + mf * 16 + r0;
                    int col = wn * 32 + nf * 8 + c0;
                    zbw[row * ZPITCH + col]           = acc[mf][nf][0];
                    zbw[row * ZPITCH + col + 1]       = acc[mf][nf][1];
                    zbw[(row + 8) * ZPITCH + col]     = acc[mf][nf][2];
                    zbw[(row + 8) * ZPITCH + col + 1] = acc[mf][nf][3];
                }
        }
        __syncthreads();

        // ---- epilogue: z = zb0 + zb1 + P; gates; c/h update (float4 LDS) ----
        {
            const float* Pr = sp + v * NTILE;
            const float* z0 = zb0 + b_local * ZPITCH;
            const float* z1 = zb1 + b_local * ZPITCH;
            union F4 { float4 v; float f[4]; };
            F4 zg, zi, zf, zo;
            {
                float4 a, b, p;
                a = *(const float4*)(z0 + jb);      b = *(const float4*)(z1 + jb);      p = *(const float4*)(Pr + jb);
                zg.v = make_float4(a.x + b.x + p.x, a.y + b.y + p.y, a.z + b.z + p.z, a.w + b.w + p.w);
                a = *(const float4*)(z0 + 16 + jb); b = *(const float4*)(z1 + 16 + jb); p = *(const float4*)(Pr + 16 + jb);
                zi.v = make_float4(a.x + b.x + p.x, a.y + b.y + p.y, a.z + b.z + p.z, a.w + b.w + p.w);
                a = *(const float4*)(z0 + 32 + jb); b = *(const float4*)(z1 + 32 + jb); p = *(const float4*)(Pr + 32 + jb);
                zf.v = make_float4(a.x + b.x + p.x, a.y + b.y + p.y, a.z + b.z + p.z, a.w + b.w + p.w);
                a = *(const float4*)(z0 + 48 + jb); b = *(const float4*)(z1 + 48 + jb); p = *(const float4*)(Pr + 48 + jb);
                zo.v = make_float4(a.x + b.x + p.x, a.y + b.y + p.y, a.z + b.z + p.z, a.w + b.w + p.w);
            }
            __half hh[4];
#pragma unroll
            for (int jj = 0; jj < 4; jj++) {
                float g  = tanhf_(zg.f[jj]);
                float ig = sigf(zi.f[jj]);
                float fg = sigf(zf.f[jj]);
                float og = sigf(zo.f[jj]);
                float cn = g * ig + creg[jj] * fg;
                creg[jj] = cn;
                hh[jj] = __float2half(tanhf_(cn) * og);
            }
            size_t ho = (size_t)b_g * HID + ntile * 16 + jb;
            *(uint2*)(g_hf[(t + 1) & 1] + ho) = *(const uint2*)hh;
        }

        // ---- grid barrier (per m-half; release-atomic publish) ----
        __syncthreads();
        if (tid == 0) {
            unsigned dummy;
            asm volatile("atom.add.release.gpu.u32 %0, [%1], 1;"
                         : "=r"(dummy) : "l"(&g_bar2[my]) : "memory");
            unsigned tgt = 64u * (unsigned)(t + 1);
            unsigned vv;
            do {
                asm volatile("ld.acquire.gpu.u32 %0, [%1];" : "=r"(vv) : "l"(&g_bar2[my]));
            } while (vv < tgt);
        }
        __syncthreads();
    }
}

// ---------------- final projection ----------------
__global__ void final_proj_kernel(const float* __restrict__ Wp, const float* __restrict__ bp,
                                  float* __restrict__ out) {
    int b = blockIdx.x;
    int tid = threadIdx.x;   // 128
    const __half* h = g_hf[0] + (size_t)b * HID;   // after 256 steps, h in buf 0
    float acc[10];
#pragma unroll
    for (int c = 0; c < 10; c++) acc[c] = 0.0f;
    for (int k = tid; k < HID; k += 128) {
        float hv = __half2float(h[k]);
#pragma unroll
        for (int c = 0; c < 10; c++) acc[c] += hv * Wp[c * HID + k];
    }
#pragma unroll
    for (int c = 0; c < 10; c++)
#pragma unroll
        for (int off = 16; off > 0; off >>= 1)
            acc[c] += __shfl_xor_sync(0xffffffffu, acc[c], off);
    __shared__ float red[4][10];
    int wid = tid >> 5, lid = tid & 31;
    if (lid == 0) {
#pragma unroll
        for (int c = 0; c < 10; c++) red[wid][c] = acc[c];
    }
    __syncthreads();
    if (tid < 10)
        out[b * 10 + tid] = red[0][tid] + red[1][tid] + red[2][tid] + red[3][tid] + bp[tid];
}

// ---------------- launch ----------------
extern "C" void kernel_launch(void* const* d_in, const int* in_sizes, int n_in,
                              void* d_out, int out_size) {
    const void*  x   = d_in[0];
    const float* embed = (const float*)d_in[1];
    const float* Wgx = (const float*)d_in[2];
    const float* Wix = (const float*)d_in[3];
    const float* Wfx = (const float*)d_in[4];
    const float* Wox = (const float*)d_in[5];
    const float* Wgh = (const float*)d_in[6];
    const float* Wih = (const float*)d_in[7];
    const float* Wfh = (const float*)d_in[8];
    const float* Woh = (const float*)d_in[9];
    const float* Wph = (const float*)d_in[10];
    const float* bg  = (const float*)d_in[11];
    const float* bi  = (const float*)d_in[12];
    const float* bf_ = (const float*)d_in[13];
    const float* bo  = (const float*)d_in[14];
    const float* bp  = (const float*)d_in[15];

    cudaFuncSetAttribute(lstm_persist, cudaFuncAttributeMaxDynamicSharedMemorySize, SMEM_TOTAL);

    zero_kernel<<<(BATCH * HID + 255) / 256, 256>>>();
    detect_convert_x<<<1, 256>>>(x);
    prep_kernel<<<G4, 128>>>(Wgx, Wix, Wfx, Wox, Wgh, Wih, Wfh, Woh, embed, bg, bi, bf_, bo);

    dim3 grid(G4 / NTILE, BATCH / MTILE);   // (64, 2) = 128 CTAs, all resident
    lstm_persist<<<grid, THREADS, SMEM_TOTAL>>>();

    final_proj_kernel<<<BATCH, 128>>>(Wph, bp, (float*)d_out);
}